// round 13
// baseline (speedup 1.0000x reference)
#include <cuda_runtime.h>
#include <cuda_fp16.h>
#include <math.h>
#include <stdint.h>

#define NB 2
#define SS 2048
#define NH 32
#define HS 80
#define HID 2560
#define H3 7680
#define H4 10240
#define ROWS (NB*SS)          // 4096

// ---------------- scratch (static device globals; no allocation) ----------------
__device__ __half g_ln[(long)ROWS * HID];
__device__ __half g_qkv[(long)ROWS * H3];
__device__ __half g_attn[(long)ROWS * HID];
__device__ __half g_fc1[(long)ROWS * H4];
__device__ float  g_res[(long)ROWS * HID];     // fp32: hidden + fc2 + biases
__device__ float  g_bsum[HID];                 // out_b + fc2_b
// transposed fp16 weights: WT[n][k] = half(W[k][n])
__device__ __half g_wqkv_t[(long)H3 * HID];
__device__ __half g_wout_t[(long)HID * HID];
__device__ __half g_w1_t[(long)H4 * HID];
__device__ __half g_w2_t[(long)HID * H4];

// ---------------- small helpers ----------------
__device__ __forceinline__ float fast_gelu(float x) {
    const float c = 0.7978845608028654f;
    float x3 = x * x * x;
    return 0.5f * x * (1.0f + tanhf(c * (x + 0.044715f * x3)));
}

__device__ __forceinline__ uint32_t smem_u32(const void* p) {
    uint32_t a;
    asm("{ .reg .u64 t; cvta.to.shared.u64 t, %1; cvt.u32.u64 %0, t; }" : "=r"(a) : "l"(p));
    return a;
}

__device__ __forceinline__ void cp16(uint32_t dst, const void* src) {
    asm volatile("cp.async.cg.shared.global [%0], [%1], 16;" :: "r"(dst), "l"(src));
}
#define CP_COMMIT() asm volatile("cp.async.commit_group;" ::: "memory")
#define CP_WAIT1()  asm volatile("cp.async.wait_group 1;" ::: "memory")
#define CP_WAIT2()  asm volatile("cp.async.wait_group 2;" ::: "memory")

__device__ __forceinline__ void mma_f16(float* d, const uint32_t* a, uint32_t b0, uint32_t b1) {
    asm volatile("mma.sync.aligned.m16n8k16.row.col.f32.f16.f16.f32 "
        "{%0,%1,%2,%3}, {%4,%5,%6,%7}, {%8,%9}, {%0,%1,%2,%3};"
        : "+f"(d[0]), "+f"(d[1]), "+f"(d[2]), "+f"(d[3])
        : "r"(a[0]), "r"(a[1]), "r"(a[2]), "r"(a[3]), "r"(b0), "r"(b1));
}

__device__ __forceinline__ void ldsm_x4(uint32_t* r, uint32_t addr) {
    asm volatile("ldmatrix.sync.aligned.m8n8.x4.shared.b16 {%0,%1,%2,%3}, [%4];"
        : "=r"(r[0]), "=r"(r[1]), "=r"(r[2]), "=r"(r[3]) : "r"(addr));
}
__device__ __forceinline__ void ldsm_x2_trans(uint32_t& r0, uint32_t& r1, uint32_t addr) {
    asm volatile("ldmatrix.sync.aligned.m8n8.x2.trans.shared.b16 {%0,%1}, [%2];"
        : "=r"(r0), "=r"(r1) : "r"(addr));
}

__device__ __forceinline__ uint32_t packh2(float a, float b) {
    __half2 h = __floats2half2_rn(a, b);
    return *reinterpret_cast<uint32_t*>(&h);
}

// ---------------- block reduce ----------------
__device__ __forceinline__ float block_reduce_sum(float v, float* sh) {
    #pragma unroll
    for (int o = 16; o > 0; o >>= 1) v += __shfl_xor_sync(0xffffffffu, v, o);
    int wid = threadIdx.x >> 5;
    if ((threadIdx.x & 31) == 0) sh[wid] = v;
    __syncthreads();
    if (threadIdx.x < 32) {
        float t = (threadIdx.x < 8) ? sh[threadIdx.x] : 0.0f;
        #pragma unroll
        for (int o = 4; o > 0; o >>= 1) t += __shfl_xor_sync(0xffffffffu, t, o);
        if (threadIdx.x == 0) sh[0] = t;
    }
    __syncthreads();
    float r = sh[0];
    __syncthreads();
    return r;
}

// ---------------- LayerNorm (fp16 output) ----------------
__global__ void ln_kernel(const float* __restrict__ x,
                          const float* __restrict__ w,
                          const float* __restrict__ b,
                          __half* __restrict__ y) {
    __shared__ float sh[8];
    long row = blockIdx.x;
    const float* xr = x + row * HID;
    __half* yr = y + row * HID;
    float vals[10];
    float sum = 0.0f;
    #pragma unroll
    for (int i = 0; i < 10; i++) { vals[i] = xr[threadIdx.x + i * 256]; sum += vals[i]; }
    float mean = block_reduce_sum(sum, sh) * (1.0f / HID);
    float sq = 0.0f;
    #pragma unroll
    for (int i = 0; i < 10; i++) { float d = vals[i] - mean; sq += d * d; }
    float var = block_reduce_sum(sq, sh) * (1.0f / HID);
    float inv = rsqrtf(var + 1e-5f);
    #pragma unroll
    for (int i = 0; i < 10; i++) {
        int idx = threadIdx.x + i * 256;
        yr[idx] = __float2half_rn((vals[i] - mean) * inv * w[idx] + b[idx]);
    }
}

// ---------------- weight transpose + fp16: WT[n][k] = half(W[k][n]) ----------------
__global__ void transpose_h_kernel(const float* __restrict__ W, __half* __restrict__ WT,
                                   int K, int N) {
    __shared__ float t[32][33];
    int k0 = blockIdx.y * 32, n0 = blockIdx.x * 32;
    int x = threadIdx.x, y = threadIdx.y;   // 32 x 8
    #pragma unroll
    for (int i = 0; i < 32; i += 8)
        t[y + i][x] = W[(long)(k0 + y + i) * N + n0 + x];
    __syncthreads();
    #pragma unroll
    for (int i = 0; i < 32; i += 8)
        WT[(long)(n0 + y + i) * K + k0 + x] = __float2half_rn(t[x][y + i]);
}

// ---------------- bias sum: g_bsum = out_b + fc2_b ----------------
__global__ void bias_sum_kernel(const float* __restrict__ a, const float* __restrict__ b,
                                float* __restrict__ c) {
    int i = blockIdx.x * 256 + threadIdx.x;
    if (i < HID) c[i] = a[i] + b[i];
}

// ================= fp16 mma GEMM infrastructure =================
#define GSTAGES 4
#define GPITCH 40
#define GSTAGE (128 * GPITCH)                     // halves per operand-stage
#define G_SMEM (GSTAGES * 2 * GSTAGE * 2)         // 81920 bytes

// compute one BK=32 step from smem stage into acc[4][4][4]; A and B both via ldmatrix
__device__ __forceinline__ void gemm_compute_stage(
    const __half* as_s, const __half* bs_s,
    int m_off, int n_off, int lane,
    float acc[4][4][4]) {
    int bi = lane >> 3, br = lane & 7;
    #pragma unroll
    for (int ks = 0; ks < 2; ks++) {
        uint32_t af[4][4];
        #pragma unroll
        for (int mt = 0; mt < 4; mt++) {
            uint32_t addr = smem_u32(as_s + (m_off + 16 * mt + (lane & 15)) * GPITCH
                                          + ks * 16 + (lane >> 4) * 8);
            ldsm_x4(af[mt], addr);
        }
        uint32_t bf[2][4];
        #pragma unroll
        for (int p = 0; p < 2; p++) {
            uint32_t addr = smem_u32(bs_s + (n_off + p * 16 + 8 * (bi >> 1) + br) * GPITCH
                                          + ks * 16 + 8 * (bi & 1));
            ldsm_x4(bf[p], addr);
        }
        #pragma unroll
        for (int mt = 0; mt < 4; mt++)
            #pragma unroll
            for (int nt = 0; nt < 4; nt++)
                mma_f16(acc[mt][nt], af[mt],
                        bf[nt >> 1][(nt & 1) * 2], bf[nt >> 1][(nt & 1) * 2 + 1]);
    }
}

// ---------------- merged QKV + FC1 GEMM (both read ln, K=HID) ----------------
__global__ __launch_bounds__(256, 2)
void gemm_qkv_fc1(const __half* __restrict__ ln,
                  const __half* __restrict__ wqkvT, const __half* __restrict__ w1T,
                  __half* __restrict__ qkv, __half* __restrict__ fc1,
                  const float* __restrict__ qkv_b, const float* __restrict__ fc1_b) {
    extern __shared__ __half hs[];
    __half* As = hs;
    __half* Bs = hs + GSTAGES * GSTAGE;

    int tid = threadIdx.x;
    int wid = tid >> 5, lane = tid & 31;
    int gid = lane >> 2, tig = lane & 3;
    int m_off = (wid >> 2) * 64;
    int n_off = (wid & 3) * 32;

    int bx = blockIdx.x;
    bool is_fc1 = bx >= (H3 / 128);
    int nb = is_fc1 ? bx - H3 / 128 : bx;
    const __half* Bb = is_fc1 ? (w1T + (long)nb * 128 * HID)
                              : (wqkvT + (long)nb * 128 * HID);
    const __half* Ab = ln + (long)blockIdx.y * 128 * HID;
    uint32_t as_u = smem_u32(As), bs_u = smem_u32(Bs);

    int lr = tid >> 2;
    int lc = (tid & 3) * 8;

    float acc[4][4][4];
    #pragma unroll
    for (int i = 0; i < 4; i++)
        #pragma unroll
        for (int j = 0; j < 4; j++)
            #pragma unroll
            for (int k = 0; k < 4; k++) acc[i][j][k] = 0.0f;

    const int iters = HID / 32;   // 80

    #pragma unroll
    for (int s = 0; s < 3; s++) {
        uint32_t off = (uint32_t)(s * GSTAGE + lr * GPITCH + lc) * 2u;
        cp16(as_u + off, Ab + (long)lr * HID + s * 32 + lc);
        cp16(bs_u + off, Bb + (long)lr * HID + s * 32 + lc);
        off += 64u * GPITCH * 2u;
        cp16(as_u + off, Ab + (long)(lr + 64) * HID + s * 32 + lc);
        cp16(bs_u + off, Bb + (long)(lr + 64) * HID + s * 32 + lc);
        CP_COMMIT();
    }

    for (int it = 0; it < iters; ++it) {
        CP_WAIT2();
        __syncthreads();
        int lt = it + 3;
        if (lt < iters) {
            int s = lt & 3;
            uint32_t off = (uint32_t)(s * GSTAGE + lr * GPITCH + lc) * 2u;
            cp16(as_u + off, Ab + (long)lr * HID + lt * 32 + lc);
            cp16(bs_u + off, Bb + (long)lr * HID + lt * 32 + lc);
            off += 64u * GPITCH * 2u;
            cp16(as_u + off, Ab + (long)(lr + 64) * HID + lt * 32 + lc);
            cp16(bs_u + off, Bb + (long)(lr + 64) * HID + lt * 32 + lc);
        }
        CP_COMMIT();
        gemm_compute_stage(As + (it & 3) * GSTAGE, Bs + (it & 3) * GSTAGE,
                           m_off, n_off, lane, acc);
    }

    const float* bias = is_fc1 ? fc1_b : qkv_b;
    int ldc = is_fc1 ? H4 : H3;
    __half* C = is_fc1 ? fc1 : qkv;
    #pragma unroll
    for (int mt = 0; mt < 4; mt++) {
        #pragma unroll
        for (int h2 = 0; h2 < 2; h2++) {
            long m = (long)blockIdx.y * 128 + m_off + 16 * mt + gid + h2 * 8;
            #pragma unroll
            for (int nt = 0; nt < 4; nt++) {
                int n = nb * 128 + n_off + 8 * nt + 2 * tig;
                float2 bv = *(const float2*)(bias + n);
                float v0 = acc[mt][nt][2 * h2 + 0] + bv.x;
                float v1 = acc[mt][nt][2 * h2 + 1] + bv.y;
                if (is_fc1) { v0 = fast_gelu(v0); v1 = fast_gelu(v1); }
                *(__half2*)(C + m * ldc + n) = __floats2half2_rn(v0, v1);
            }
        }
    }
}

// ---------------- generic fp32-accumulating GEMM: C = R + A@B^T (+bias) ----------------
// nbx0: N-block offset (for column-split launches)
template<bool HAS_BIAS>
__global__ __launch_bounds__(256, 2)
void gemm_addf32(const __half* __restrict__ A, int lda,
                 const __half* __restrict__ B, int ldb,
                 int K, int nbx0,
                 const float* __restrict__ R, const float* __restrict__ bias,
                 float* __restrict__ C) {
    extern __shared__ __half hs[];
    __half* As = hs;
    __half* Bs = hs + GSTAGES * GSTAGE;

    int tid = threadIdx.x;
    int wid = tid >> 5, lane = tid & 31;
    int gid = lane >> 2, tig = lane & 3;
    int m_off = (wid >> 2) * 64;
    int n_off = (wid & 3) * 32;

    int nb = blockIdx.x + nbx0;
    const __half* Ab = A + (long)blockIdx.y * 128 * lda;
    const __half* Bb = B + (long)nb * 128 * ldb;
    uint32_t as_u = smem_u32(As), bs_u = smem_u32(Bs);

    int lr = tid >> 2;
    int lc = (tid & 3) * 8;

    float acc[4][4][4];
    #pragma unroll
    for (int i = 0; i < 4; i++)
        #pragma unroll
        for (int j = 0; j < 4; j++)
            #pragma unroll
            for (int k = 0; k < 4; k++) acc[i][j][k] = 0.0f;

    int iters = K / 32;

    #pragma unroll
    for (int s = 0; s < 3; s++) {
        uint32_t off = (uint32_t)(s * GSTAGE + lr * GPITCH + lc) * 2u;
        cp16(as_u + off, Ab + (long)lr * lda + s * 32 + lc);
        cp16(bs_u + off, Bb + (long)lr * ldb + s * 32 + lc);
        off += 64u * GPITCH * 2u;
        cp16(as_u + off, Ab + (long)(lr + 64) * lda + s * 32 + lc);
        cp16(bs_u + off, Bb + (long)(lr + 64) * ldb + s * 32 + lc);
        CP_COMMIT();
    }

    for (int it = 0; it < iters; ++it) {
        CP_WAIT2();
        __syncthreads();
        int lt = it + 3;
        if (lt < iters) {
            int s = lt & 3;
            uint32_t off = (uint32_t)(s * GSTAGE + lr * GPITCH + lc) * 2u;
            cp16(as_u + off, Ab + (long)lr * lda + lt * 32 + lc);
            cp16(bs_u + off, Bb + (long)lr * ldb + lt * 32 + lc);
            off += 64u * GPITCH * 2u;
            cp16(as_u + off, Ab + (long)(lr + 64) * lda + lt * 32 + lc);
            cp16(bs_u + off, Bb + (long)(lr + 64) * ldb + lt * 32 + lc);
        }
        CP_COMMIT();
        gemm_compute_stage(As + (it & 3) * GSTAGE, Bs + (it & 3) * GSTAGE,
                           m_off, n_off, lane, acc);
    }

    #pragma unroll
    for (int mt = 0; mt < 4; mt++) {
        #pragma unroll
        for (int h2 = 0; h2 < 2; h2++) {
            long m = (long)blockIdx.y * 128 + m_off + 16 * mt + gid + h2 * 8;
            #pragma unroll
            for (int nt = 0; nt < 4; nt++) {
                int n = nb * 128 + n_off + 8 * nt + 2 * tig;
                float2 r = *(const float2*)(R + m * HID + n);
                float v0 = acc[mt][nt][2 * h2 + 0] + r.x;
                float v1 = acc[mt][nt][2 * h2 + 1] + r.y;
                if (HAS_BIAS) {
                    float2 bv = *(const float2*)(bias + n);
                    v0 += bv.x; v1 += bv.y;
                }
                *(float2*)(C + m * HID + n) = make_float2(v0, v1);
            }
        }
    }
}

// ---------------- partial RoPE (in-place on fp16 q,k) ----------------
__global__ void rope_kernel(__half* __restrict__ qkv) {
    int idx = blockIdx.x * blockDim.x + threadIdx.x;
    const int total = NB * SS * NH * 16;
    if (idx >= total) return;
    int p = idx & 15;
    int h = (idx >> 4) & 31;
    int s = (idx >> 9) & (SS - 1);
    int b = idx >> 20;
    float inv = __expf(-(float)p * (9.210340371976184f / 16.0f));
    float angle = (float)s * inv;
    float sn, cs;
    sincosf(angle, &sn, &cs);
    long base = ((long)b * SS + s) * H3 + (long)h * HS;
    __half* qp = qkv + base;
    __half* kp = qkv + base + HID;
    float q1 = __half2float(qp[p]), q2 = __half2float(qp[p + 16]);
    qp[p]      = __float2half_rn(q1 * cs - q2 * sn);
    qp[p + 16] = __float2half_rn(q1 * sn + q2 * cs);
    float k1 = __half2float(kp[p]), k2 = __half2float(kp[p + 16]);
    kp[p]      = __float2half_rn(k1 * cs - k2 * sn);
    kp[p + 16] = __float2half_rn(k1 * sn + k2 * cs);
}

// ================= fp16 flash attention (3-stage, single sync/iter) =================
#define FBQ 128
#define FBK 64
#define KVP 88
#define FSTAGE (FBK * KVP)
#define FLASH_SMEM (3 * 2 * FSTAGE * 2)          // 67584 bytes

__global__ __launch_bounds__(256, 1)
void flash_h(const __half* __restrict__ qkv, __half* __restrict__ attn) {
    extern __shared__ __half fs[];
    __half* Ks = fs;
    __half* Vs = fs + 3 * FSTAGE;

    int tid = threadIdx.x, wid = tid >> 5, lane = tid & 31;
    int gid = lane >> 2, tig = lane & 3;
    int qt = (int)gridDim.x - 1 - blockIdx.x;
    int q0 = qt * FBQ;
    int b = blockIdx.y >> 5, h = blockIdx.y & 31;
    int m0 = wid * 16;

    const __half* qbase = qkv + (long)b * SS * H3 + (long)h * HS;
    const __half* kbase = qbase + HID;
    const __half* vbase = qbase + 2 * HID;

    int row0 = q0 + m0 + gid;
    int row1 = row0 + 8;

    uint32_t qf[5][4];
    {
        const __half* q0p = qbase + (long)row0 * H3;
        const __half* q1p = qbase + (long)row1 * H3;
        #pragma unroll
        for (int g = 0; g < 5; g++) {
            qf[g][0] = *(const uint32_t*)(q0p + 16 * g + 2 * tig);
            qf[g][1] = *(const uint32_t*)(q1p + 16 * g + 2 * tig);
            qf[g][2] = *(const uint32_t*)(q0p + 16 * g + 8 + 2 * tig);
            qf[g][3] = *(const uint32_t*)(q1p + 16 * g + 8 + 2 * tig);
        }
    }

    float oacc[10][4];
    #pragma unroll
    for (int i = 0; i < 10; i++)
        #pragma unroll
        for (int j = 0; j < 4; j++) oacc[i][j] = 0.0f;
    float mrow0 = -1e30f, mrow1 = -1e30f, lrow0 = 0.0f, lrow1 = 0.0f;

    int ntiles = q0 / FBK + 2;
    uint32_t ks_u = smem_u32(Ks), vs_u = smem_u32(Vs);

    auto issue_tile = [&](int t, int stage) {
        int kv = t * FBK;
        #pragma unroll
        for (int i = 0; i < 3; i++) {
            int c = tid + i * 256;
            if (c < 640) {
                int r = c / 10, cc = c % 10;
                uint32_t off = (uint32_t)((stage * FBK + r) * KVP + cc * 8) * 2u;
                cp16(ks_u + off, kbase + (long)(kv + r) * H3 + cc * 8);
                cp16(vs_u + off, vbase + (long)(kv + r) * H3 + cc * 8);
            }
        }
    };

    issue_tile(0, 0); CP_COMMIT();
    issue_tile(1, 1); CP_COMMIT();

    const float scale = 0.11180339887498949f;

    for (int t = 0; t < ntiles; ++t) {
        CP_WAIT1();
        __syncthreads();
        if (t + 2 < ntiles) issue_tile(t + 2, (t + 2) % 3);
        CP_COMMIT();
        int stage = t % 3;

        float sacc[8][4];
        #pragma unroll
        for (int i = 0; i < 8; i++)
            #pragma unroll
            for (int j = 0; j < 4; j++) sacc[i][j] = 0.0f;

        const __half* kt = Ks + stage * FSTAGE;
        #pragma unroll
        for (int nt = 0; nt < 8; nt++) {
            const uint32_t* bp = (const uint32_t*)(kt + (8 * nt + gid) * KVP);
            #pragma unroll
            for (int g = 0; g < 5; g++)
                mma_f16(sacc[nt], qf[g], bp[8 * g + tig], bp[8 * g + 4 + tig]);
        }

        int kv0 = t * FBK;
        bool need_mask = (t >= ntiles - 2);
        #pragma unroll
        for (int nt = 0; nt < 8; nt++) {
            int c0 = kv0 + nt * 8 + 2 * tig;
            #pragma unroll
            for (int j = 0; j < 4; j++) sacc[nt][j] *= scale;
            if (need_mask) {
                if (c0 > row0)     sacc[nt][0] = -1e30f;
                if (c0 + 1 > row0) sacc[nt][1] = -1e30f;
                if (c0 > row1)     sacc[nt][2] = -1e30f;
                if (c0 + 1 > row1) sacc[nt][3] = -1e30f;
            }
        }

        float rm0 = -1e30f, rm1 = -1e30f;
        #pragma unroll
        for (int nt = 0; nt < 8; nt++) {
            rm0 = fmaxf(rm0, fmaxf(sacc[nt][0], sacc[nt][1]));
            rm1 = fmaxf(rm1, fmaxf(sacc[nt][2], sacc[nt][3]));
        }
        rm0 = fmaxf(rm0, __shfl_xor_sync(0xffffffffu, rm0, 1));
        rm0 = fmaxf(rm0, __shfl_xor_sync(0xffffffffu, rm0, 2));
        rm1 = fmaxf(rm1, __shfl_xor_sync(0xffffffffu, rm1, 1));
        rm1 = fmaxf(rm1, __shfl_xor_sync(0xffffffffu, rm1, 2));
        float mn0 = fmaxf(mrow0, rm0);
        float mn1 = fmaxf(mrow1, rm1);

        float rs0 = 0.0f, rs1 = 0.0f;
        uint32_t ph[8][2];
        #pragma unroll
        for (int nt = 0; nt < 8; nt++) {
            float p0 = __expf(sacc[nt][0] - mn0);
            float p1 = __expf(sacc[nt][1] - mn0);
            float p2 = __expf(sacc[nt][2] - mn1);
            float p3 = __expf(sacc[nt][3] - mn1);
            rs0 += p0 + p1;
            rs1 += p2 + p3;
            ph[nt][0] = packh2(p0, p1);
            ph[nt][1] = packh2(p2, p3);
        }
        rs0 += __shfl_xor_sync(0xffffffffu, rs0, 1);
        rs0 += __shfl_xor_sync(0xffffffffu, rs0, 2);
        rs1 += __shfl_xor_sync(0xffffffffu, rs1, 1);
        rs1 += __shfl_xor_sync(0xffffffffu, rs1, 2);

        float a0 = __expf(mrow0 - mn0);
        float a1 = __expf(mrow1 - mn1);
        lrow0 = lrow0 * a0 + rs0;
        lrow1 = lrow1 * a1 + rs1;
        mrow0 = mn0; mrow1 = mn1;
        #pragma unroll
        for (int nt = 0; nt < 10; nt++) {
            oacc[nt][0] *= a0; oacc[nt][1] *= a0;
            oacc[nt][2] *= a1; oacc[nt][3] *= a1;
        }

        const __half* vt = Vs + stage * FSTAGE;
        #pragma unroll
        for (int g = 0; g < 4; g++) {
            uint32_t af[4] = { ph[2 * g][0], ph[2 * g][1], ph[2 * g + 1][0], ph[2 * g + 1][1] };
            #pragma unroll
            for (int nt = 0; nt < 10; nt++) {
                uint32_t b0, b1;
                uint32_t addr = smem_u32(vt + (16 * g + (lane & 15)) * KVP + nt * 8);
                ldsm_x2_trans(b0, b1, addr);
                mma_f16(oacc[nt], af, b0, b1);
            }
        }
    }

    float inv0 = 1.0f / lrow0;
    float inv1 = 1.0f / lrow1;
    __half* o0 = attn + ((long)b * SS + row0) * HID + h * HS;
    __half* o1 = attn + ((long)b * SS + row1) * HID + h * HS;
    #pragma unroll
    for (int nt = 0; nt < 10; nt++) {
        int cc = nt * 8 + 2 * tig;
        *(__half2*)(o0 + cc) = __floats2half2_rn(oacc[nt][0] * inv0, oacc[nt][1] * inv0);
        *(__half2*)(o1 + cc) = __floats2half2_rn(oacc[nt][2] * inv1, oacc[nt][3] * inv1);
    }
}

// ---------------- host-side launcher ----------------
static void* sym_addr(const void* symbol) {
    void* p = nullptr;
    cudaGetSymbolAddress(&p, symbol);
    return p;
}

#define FC2_SPLIT 14   // of 20 N-blocks on side stream; rest on main after flash

extern "C" void kernel_launch(void* const* d_in, const int* in_sizes, int n_in,
                              void* d_out, int out_size) {
    const float* hidden = (const float*)d_in[0];
    const float* ln_w   = (const float*)d_in[1];
    const float* ln_b   = (const float*)d_in[2];
    const float* qkv_w  = (const float*)d_in[3];
    const float* qkv_b  = (const float*)d_in[4];
    const float* out_w  = (const float*)d_in[5];
    const float* out_b  = (const float*)d_in[6];
    const float* fc1_w  = (const float*)d_in[7];
    const float* fc1_b  = (const float*)d_in[8];
    const float* fc2_w  = (const float*)d_in[9];
    const float* fc2_b  = (const float*)d_in[10];
    float* out = (float*)d_out;

    __half* ln    = (__half*)sym_addr(g_ln);
    __half* qkv   = (__half*)sym_addr(g_qkv);
    __half* attn  = (__half*)sym_addr(g_attn);
    __half* fc1   = (__half*)sym_addr(g_fc1);
    float*  res   = (float*)sym_addr(g_res);
    float*  bsum  = (float*)sym_addr(g_bsum);
    __half* wqkvT = (__half*)sym_addr(g_wqkv_t);
    __half* woutT = (__half*)sym_addr(g_wout_t);
    __half* w1T   = (__half*)sym_addr(g_w1_t);
    __half* w2T   = (__half*)sym_addr(g_w2_t);

    cudaFuncSetAttribute(gemm_qkv_fc1, cudaFuncAttributeMaxDynamicSharedMemorySize, G_SMEM);
    cudaFuncSetAttribute(gemm_addf32<true>, cudaFuncAttributeMaxDynamicSharedMemorySize, G_SMEM);
    cudaFuncSetAttribute(gemm_addf32<false>, cudaFuncAttributeMaxDynamicSharedMemorySize, G_SMEM);
    cudaFuncSetAttribute(flash_h, cudaFuncAttributeMaxDynamicSharedMemorySize, FLASH_SMEM);

    // ONE side stream + events (matches the footprint that passed in R10's run)
    cudaStream_t s2;
    cudaStreamCreateWithFlags(&s2, cudaStreamNonBlocking);
    cudaEvent_t ev_root, ev_g1, ev_s3a, ev_fc2a;
    cudaEventCreateWithFlags(&ev_root, cudaEventDisableTiming);
    cudaEventCreateWithFlags(&ev_g1, cudaEventDisableTiming);
    cudaEventCreateWithFlags(&ev_s3a, cudaEventDisableTiming);
    cudaEventCreateWithFlags(&ev_fc2a, cudaEventDisableTiming);

    dim3 tblk(32, 8);

    // main: transposes needed by qkv_fc1, then LN
    transpose_h_kernel<<<dim3(H3 / 32, HID / 32), tblk>>>(qkv_w, wqkvT, HID, H3);
    transpose_h_kernel<<<dim3(H4 / 32, HID / 32), tblk>>>(fc1_w, w1T, HID, H4);
    ln_kernel<<<ROWS, 256>>>(hidden, ln_w, ln_b, ln);

    // capture-legal fork: s2 first waits on an event recorded on the capturing stream
    cudaEventRecord(ev_root, 0);
    cudaStreamWaitEvent(s2, ev_root, 0);

    // s2: bias + w2T (needed by fc2), then woutT (needed by outproj),
    // all overlapping the big GEMM on main
    bias_sum_kernel<<<(HID + 255) / 256, 256, 0, s2>>>(out_b, fc2_b, bsum);
    transpose_h_kernel<<<dim3(HID / 32, H4 / 32), tblk, 0, s2>>>(fc2_w, w2T, H4, HID);
    cudaEventRecord(ev_s3a, s2);
    transpose_h_kernel<<<dim3(HID / 32, HID / 32), tblk, 0, s2>>>(out_w, woutT, HID, HID);

    // main: merged QKV+FC1 GEMM
    gemm_qkv_fc1<<<dim3(H3 / 128 + H4 / 128, ROWS / 128), 256, G_SMEM>>>(
        ln, wqkvT, w1T, qkv, fc1, qkv_b, fc1_b);
    cudaEventRecord(ev_g1, 0);

    // s2: fc2a = hidden + fc1@W2 + bsum (columns 0..FC2_SPLIT-1), overlaps flash
    cudaStreamWaitEvent(s2, ev_g1, 0);
    gemm_addf32<true><<<dim3(FC2_SPLIT, ROWS / 128), 256, G_SMEM, s2>>>(
        fc1, H4, w2T, H4, H4, 0, hidden, bsum, res);
    cudaEventRecord(ev_fc2a, s2);

    // main: rope + flash
    {
        int total = NB * SS * NH * 16;
        rope_kernel<<<(total + 255) / 256, 256>>>(qkv);
    }
    flash_h<<<dim3(SS / FBQ, NB * NH), 256, FLASH_SMEM>>>(qkv, attn);

    // main: fc2b (remaining columns; needs w2T via ev_s3a)
    cudaStreamWaitEvent(0, ev_s3a, 0);
    gemm_addf32<true><<<dim3(HID / 128 - FC2_SPLIT, ROWS / 128), 256, G_SMEM>>>(
        fc1, H4, w2T, H4, H4, FC2_SPLIT, hidden, bsum, res);

    // join (ev_fc2a also orders woutT, which precedes fc2a on s2), then
    // out = res + attn@Wo
    cudaStreamWaitEvent(0, ev_fc2a, 0);
    gemm_addf32<false><<<dim3(HID / 128, ROWS / 128), 256, G_SMEM>>>(
        attn, HID, woutT, HID, HID, 0, res, nullptr, out);
}